// round 7
// baseline (speedup 1.0000x reference)
#include <cuda_runtime.h>
#include <cstdint>

// VoxelHashTable: 2-level hash-grid trilinear interpolation.
// Inputs (metadata order):
//   d_in[0] query_pts (M,3) f32
//   d_in[1] feats0    (n0,32) f32
//   d_in[2] feats1    (n1,32) f32
//   d_in[3] h2v0      (2^20) i32
//   d_in[4] h2v1      (2^20) i32
// Output: (M, 64) f32  — [level0 32 | level1 32]
//
// Warp layout (1 warp = 4 queries, processed as two pipelined pairs A and B):
//   half  = lane>>4        which query of the current pair
//   level = (lane>>3)&1    resolution level this lane serves
//   s     = lane&7         channel chunk (floats 4s..4s+3)
// Prologue: hash lookups for BOTH pairs issued back-to-back (2 independent
// scattered LDGs per lane) so pair B's hash latency hides behind pair A's
// gather. Gather: 8 predicated 128B row loads per pair (invalid corners skip
// their load entirely). Each lane's accumulator is exactly
// output[query*64 + level*32 + 4s..4s+3]; stores are 512B coalesced per warp.

#define TSIZE_MASK ((1 << 20) - 1)

// PRIMES % 2^20 (exact):
#define PMX 455773
#define PMY 475301
#define PMZ 655287

__global__ __launch_bounds__(256, 7) void voxel_hash_kernel(
    const float* __restrict__ q,
    const float* __restrict__ f0,
    const float* __restrict__ f1,
    const int* __restrict__ h0,
    const int* __restrict__ h1,
    float* __restrict__ out,
    int M)
{
    const int wid  = (blockIdx.x * blockDim.x + threadIdx.x) >> 5;
    const int lane = threadIdx.x & 31;

    const int level = (lane >> 3) & 1;  // this lane's resolution level
    const int s     = lane & 7;         // float4 chunk within the 32-dim feature
    const int half  = lane >> 4;        // which query of the pair

    const int base = wid * 4;
    int qA = base + half;
    int qB = base + 2 + half;
    const bool actA = qA < M;
    const bool actB = qB < M;
    if (qA >= M) qA = M - 1;
    if (qB >= M) qB = M - 1;

    const float res = level ? 0.24f : 0.12f;   // 0.24f == float32(0.12*2.0)
    const int*   __restrict__ hp = level ? h1 : h0;
    const float* __restrict__ fp = (level ? f1 : f0) + s * 4;
    const int src_base = lane & 0x18;          // (half<<4) | (level<<3)
    const int oxb = (lane >> 2) & 1;
    const int oyb = (lane >> 1) & 1;
    const int ozb = lane & 1;

    // ---- Prologue: both pairs' query points + hash lookups ----
    const float qAx = __ldg(q + qA * 3 + 0);
    const float qAy = __ldg(q + qA * 3 + 1);
    const float qAz = __ldg(q + qA * 3 + 2);
    const float qBx = __ldg(q + qB * 3 + 0);
    const float qBy = __ldg(q + qB * 3 + 1);
    const float qBz = __ldg(q + qB * 3 + 2);

    const float sxA = __fdiv_rn(qAx, res);
    const float syA = __fdiv_rn(qAy, res);
    const float szA = __fdiv_rn(qAz, res);
    const float bxA = floorf(sxA), byA = floorf(syA), bzA = floorf(szA);
    const float fxA = sxA - bxA, fyA = syA - byA, fzA = szA - bzA;

    int vidxA;
    {
        const unsigned hv = ((unsigned)(((int)bxA + oxb) * PMX +
                                        ((int)byA + oyb) * PMY +
                                        ((int)bzA + ozb) * PMZ)) & TSIZE_MASK;
        vidxA = __ldg(hp + hv);
    }

    const float sxB = __fdiv_rn(qBx, res);
    const float syB = __fdiv_rn(qBy, res);
    const float szB = __fdiv_rn(qBz, res);
    const float bxB = floorf(sxB), byB = floorf(syB), bzB = floorf(szB);
    const float fxB = sxB - bxB, fyB = syB - byB, fzB = szB - bzB;

    int vidxB;
    {
        const unsigned hv = ((unsigned)(((int)bxB + oxb) * PMX +
                                        ((int)byB + oyb) * PMY +
                                        ((int)bzB + ozb) * PMZ)) & TSIZE_MASK;
        vidxB = __ldg(hp + hv);
    }

    // ---- Gather A ----
    {
        const float gx = 1.0f - fxA, gy = 1.0f - fyA, gz = 1.0f - fzA;
        float4 acc = make_float4(0.f, 0.f, 0.f, 0.f);
        #pragma unroll
        for (int t = 0; t < 8; ++t) {
            const int v = __shfl_sync(0xFFFFFFFFu, vidxA, src_base + t);
            // ((wx*wy)*wz) multiply order matches reference prod(axis=2).
            const float w = ((t & 4) ? fxA : gx) *
                            ((t & 2) ? fyA : gy) *
                            ((t & 1) ? fzA : gz);
            if (v >= 0) {
                const float4 f = __ldg((const float4*)(fp + (size_t)v * 32));
                acc.x = fmaf(f.x, w, acc.x);
                acc.y = fmaf(f.y, w, acc.y);
                acc.z = fmaf(f.z, w, acc.z);
                acc.w = fmaf(f.w, w, acc.w);
            }
        }
        if (actA) {
            *(float4*)(out + (size_t)qA * 64 + level * 32 + s * 4) = acc;
        }
    }

    // ---- Gather B ----
    {
        const float gx = 1.0f - fxB, gy = 1.0f - fyB, gz = 1.0f - fzB;
        float4 acc = make_float4(0.f, 0.f, 0.f, 0.f);
        #pragma unroll
        for (int t = 0; t < 8; ++t) {
            const int v = __shfl_sync(0xFFFFFFFFu, vidxB, src_base + t);
            const float w = ((t & 4) ? fxB : gx) *
                            ((t & 2) ? fyB : gy) *
                            ((t & 1) ? fzB : gz);
            if (v >= 0) {
                const float4 f = __ldg((const float4*)(fp + (size_t)v * 32));
                acc.x = fmaf(f.x, w, acc.x);
                acc.y = fmaf(f.y, w, acc.y);
                acc.z = fmaf(f.z, w, acc.z);
                acc.w = fmaf(f.w, w, acc.w);
            }
        }
        if (actB) {
            *(float4*)(out + (size_t)qB * 64 + level * 32 + s * 4) = acc;
        }
    }
}

extern "C" void kernel_launch(void* const* d_in, const int* in_sizes, int n_in,
                              void* d_out, int out_size)
{
    const float* q  = (const float*)d_in[0];
    const float* f0 = (const float*)d_in[1];
    const float* f1 = (const float*)d_in[2];
    const int*   h0 = (const int*)d_in[3];
    const int*   h1 = (const int*)d_in[4];
    float* out = (float*)d_out;

    const int M = in_sizes[0] / 3;
    const int warps = (M + 3) / 4;          // 4 queries per warp

    const int warps_per_block = 8;
    const int blocks = (warps + warps_per_block - 1) / warps_per_block;
    voxel_hash_kernel<<<blocks, warps_per_block * 32>>>(q, f0, f1, h0, h1, out, M);
}

// round 8
// speedup vs baseline: 1.5787x; 1.5787x over previous
#include <cuda_runtime.h>
#include <cstdint>

// VoxelHashTable: 2-level hash-grid trilinear interpolation.
// Inputs (metadata order):
//   d_in[0] query_pts (M,3) f32
//   d_in[1] feats0    (n0,32) f32
//   d_in[2] feats1    (n1,32) f32
//   d_in[3] h2v0      (2^20) i32
//   d_in[4] h2v1      (2^20) i32
// Output: (M, 64) f32  — [level0 32 | level1 32]
//
// Warp layout (1 warp = 4 queries, two software-pipelined pairs A, B):
//   half  = lane>>4        which query of the current pair
//   level = (lane>>3)&1    resolution level this lane serves
//   s     = lane&7         channel chunk (floats 4s..4s+3)
// Prologue issues BOTH pairs' hash LDGs back-to-back so pair B's L2 latency
// hides under pair A's gather. Gathers use predicated 128B row loads.
//
// __launch_bounds__(256, 6): 40-reg budget (reg granularity is 8; the R6
// attempt at (256,7) got truncated to 32 regs and SPILLED the pipeline carry,
// which is what regressed it). 48 warps/SM (75% occ) + doubled per-warp MLP.

#define TSIZE_MASK ((1 << 20) - 1)

// PRIMES % 2^20 (exact):
#define PMX 455773
#define PMY 475301
#define PMZ 655287

__global__ __launch_bounds__(256, 6) void voxel_hash_kernel(
    const float* __restrict__ q,
    const float* __restrict__ f0,
    const float* __restrict__ f1,
    const int* __restrict__ h0,
    const int* __restrict__ h1,
    float* __restrict__ out,
    int M)
{
    const int wid  = (blockIdx.x * blockDim.x + threadIdx.x) >> 5;
    const int lane = threadIdx.x & 31;

    const int level = (lane >> 3) & 1;
    const int s     = lane & 7;
    const int half  = lane >> 4;

    const int base = wid * 4;
    int qA = base + half;
    int qB = base + 2 + half;
    const bool actA = qA < M;
    const bool actB = qB < M;
    if (qA >= M) qA = M - 1;
    if (qB >= M) qB = M - 1;

    const float res = level ? 0.24f : 0.12f;   // 0.24f == float32(0.12*2.0)
    const int*   __restrict__ hp = level ? h1 : h0;
    const float* __restrict__ fp = (level ? f1 : f0) + s * 4;
    const int src_base = lane & 0x18;          // (half<<4) | (level<<3)
    const int oxb = (lane >> 2) & 1;
    const int oyb = (lane >> 1) & 1;
    const int ozb = lane & 1;

    // ---- Prologue: both pairs' query points + hash lookups in flight ----
    const float qAx = __ldg(q + qA * 3 + 0);
    const float qAy = __ldg(q + qA * 3 + 1);
    const float qAz = __ldg(q + qA * 3 + 2);
    const float qBx = __ldg(q + qB * 3 + 0);
    const float qBy = __ldg(q + qB * 3 + 1);
    const float qBz = __ldg(q + qB * 3 + 2);

    const float sxA = __fdiv_rn(qAx, res);
    const float syA = __fdiv_rn(qAy, res);
    const float szA = __fdiv_rn(qAz, res);
    const float bxA = floorf(sxA), byA = floorf(syA), bzA = floorf(szA);
    const float fxA = sxA - bxA, fyA = syA - byA, fzA = szA - bzA;

    int vidxA;
    {
        const unsigned hv = ((unsigned)(((int)bxA + oxb) * PMX +
                                        ((int)byA + oyb) * PMY +
                                        ((int)bzA + ozb) * PMZ)) & TSIZE_MASK;
        vidxA = __ldg(hp + hv);
    }

    const float sxB = __fdiv_rn(qBx, res);
    const float syB = __fdiv_rn(qBy, res);
    const float szB = __fdiv_rn(qBz, res);
    const float bxB = floorf(sxB), byB = floorf(syB), bzB = floorf(szB);
    const float fxB = sxB - bxB, fyB = syB - byB, fzB = szB - bzB;

    int vidxB;
    {
        const unsigned hv = ((unsigned)(((int)bxB + oxb) * PMX +
                                        ((int)byB + oyb) * PMY +
                                        ((int)bzB + ozb) * PMZ)) & TSIZE_MASK;
        vidxB = __ldg(hp + hv);
    }

    // ---- Gather A ----
    {
        const float gx = 1.0f - fxA, gy = 1.0f - fyA, gz = 1.0f - fzA;
        float4 acc = make_float4(0.f, 0.f, 0.f, 0.f);
        #pragma unroll
        for (int t = 0; t < 8; ++t) {
            const int v = __shfl_sync(0xFFFFFFFFu, vidxA, src_base + t);
            // ((wx*wy)*wz) multiply order matches reference prod(axis=2).
            const float w = ((t & 4) ? fxA : gx) *
                            ((t & 2) ? fyA : gy) *
                            ((t & 1) ? fzA : gz);
            if (v >= 0) {
                const float4 f = __ldg((const float4*)(fp + (size_t)v * 32));
                acc.x = fmaf(f.x, w, acc.x);
                acc.y = fmaf(f.y, w, acc.y);
                acc.z = fmaf(f.z, w, acc.z);
                acc.w = fmaf(f.w, w, acc.w);
            }
        }
        if (actA) {
            *(float4*)(out + (size_t)qA * 64 + level * 32 + s * 4) = acc;
        }
    }

    // ---- Gather B ----
    {
        const float gx = 1.0f - fxB, gy = 1.0f - fyB, gz = 1.0f - fzB;
        float4 acc = make_float4(0.f, 0.f, 0.f, 0.f);
        #pragma unroll
        for (int t = 0; t < 8; ++t) {
            const int v = __shfl_sync(0xFFFFFFFFu, vidxB, src_base + t);
            const float w = ((t & 4) ? fxB : gx) *
                            ((t & 2) ? fyB : gy) *
                            ((t & 1) ? fzB : gz);
            if (v >= 0) {
                const float4 f = __ldg((const float4*)(fp + (size_t)v * 32));
                acc.x = fmaf(f.x, w, acc.x);
                acc.y = fmaf(f.y, w, acc.y);
                acc.z = fmaf(f.z, w, acc.z);
                acc.w = fmaf(f.w, w, acc.w);
            }
        }
        if (actB) {
            *(float4*)(out + (size_t)qB * 64 + level * 32 + s * 4) = acc;
        }
    }
}

extern "C" void kernel_launch(void* const* d_in, const int* in_sizes, int n_in,
                              void* d_out, int out_size)
{
    const float* q  = (const float*)d_in[0];
    const float* f0 = (const float*)d_in[1];
    const float* f1 = (const float*)d_in[2];
    const int*   h0 = (const int*)d_in[3];
    const int*   h1 = (const int*)d_in[4];
    float* out = (float*)d_out;

    const int M = in_sizes[0] / 3;
    const int warps = (M + 3) / 4;          // 4 queries per warp

    const int warps_per_block = 8;
    const int blocks = (warps + warps_per_block - 1) / warps_per_block;
    voxel_hash_kernel<<<blocks, warps_per_block * 32>>>(q, f0, f1, h0, h1, out, M);
}